// round 11
// baseline (speedup 1.0000x reference)
#include <cuda_runtime.h>

// ---------------------------------------------------------------------------
// CrossWindowAttention3D: 3D shifted-window attention (Video-Swin style)
//   spatial 48^3, C=96, heads=4 (hd=24), window 6^3 (216 tokens), shift 3
// Round 11: balance RF-bytes vs FMA (LDS.128 = 4 wavefronts regardless of
//   broadcast). GEMM 8co x 8vox @ 288 thr (tile 96x192, 2 CTA/SM, 18 warps).
//   Attention: lane-pair dim-split x 4 queries/pair (wf:FMA = 1:1), logit
//   halves exchanged via shfl_xor, bias prefetched 4 keys ahead.
// ---------------------------------------------------------------------------

#define VOX   110592            // 48*48*48
#define NC    96
#define NH    4
#define HD    24
#define NTOK  216               // 6*6*6
#define NWIN  512               // 8*8*8
#define LOG2E 1.4426950408889634f
#define MASKC (-100.0f * LOG2E)
#define WS    100               // W smem row stride (floats); 400 B rows (16B-mult)
#define GV    192               // GEMM vox tile
#define GT    288               // GEMM threads

// Scratch (device globals: allocation-free rule)
__device__ float g_q[NC * VOX];
__device__ float g_k[NC * VOX];
__device__ float g_v[NC * VOX];
__device__ float g_o[NC * VOX];
__device__ float g_biasT[NH * NTOK * NTOK];   // [head][key j][query i], *log2(e)

typedef unsigned long long u64;

__device__ __forceinline__ float ex2f(float x) {
    float r;
    asm("ex2.approx.ftz.f32 %0, %1;" : "=f"(r) : "f"(x));
    return r;
}
// packed f32x2 ops (sm_103a FFMA2/FADD2 — only reachable via PTX f32x2 forms)
__device__ __forceinline__ u64 fma2(u64 a, u64 b, u64 c) {
    u64 d;
    asm("fma.rn.f32x2 %0, %1, %2, %3;" : "=l"(d) : "l"(a), "l"(b), "l"(c));
    return d;
}
__device__ __forceinline__ u64 add2(u64 a, u64 b) {
    u64 d;
    asm("add.rn.f32x2 %0, %1, %2;" : "=l"(d) : "l"(a), "l"(b));
    return d;
}
__device__ __forceinline__ u64 splat2(float x) {
    u64 d;
    asm("mov.b64 %0, {%1, %1};" : "=l"(d) : "f"(x));
    return d;
}
__device__ __forceinline__ u64 pack2(float lo, float hi) {
    u64 d;
    asm("mov.b64 %0, {%1, %2};" : "=l"(d) : "f"(lo), "f"(hi));
    return d;
}
__device__ __forceinline__ float hadd2(u64 a) {
    float lo, hi;
    asm("mov.b64 {%0, %1}, %2;" : "=f"(lo), "=f"(hi) : "l"(a));
    return lo + hi;
}
__device__ __forceinline__ float2 unpack2(u64 a) {
    float lo, hi;
    asm("mov.b64 {%0, %1}, %2;" : "=f"(lo), "=f"(hi) : "l"(a));
    return make_float2(lo, hi);
}

// ---------------------------------------------------------------------------
// Relative-position bias table, transposed to [h][j][i], premultiplied log2e.
// ---------------------------------------------------------------------------
extern "C" __global__ void bias_prep(const float* __restrict__ rel_table)
{
    int j = blockIdx.x;      // key token
    int i = threadIdx.x;     // query token
    int iz = i / 36, iy = (i / 6) % 6, ix = i % 6;
    int jz = j / 36, jy = (j / 6) % 6, jx = j % 6;
    int idx = ((iz - jz + 5) * 11 + (iy - jy + 5)) * 11 + (ix - jx + 5);
#pragma unroll
    for (int h = 0; h < NH; h++)
        g_biasT[h * (NTOK * NTOK) + j * NTOK + i] = rel_table[idx * NH + h] * LOG2E;
}

// ---------------------------------------------------------------------------
// GEMM: Y[96][VOX] = (W[96x96] @ X[96][VOX] + bias) * outScale
// CTA: 96 cout x 192 vox, 288 threads, thread tile 8 cout x 8 vox.
// Per k per thread: 64 B loaded, 32 FFMA2 -> wavefronts : FMA-cyc = 1 : 1.
// smem 112128 B/CTA -> 2 CTA/SM (18 warps).
// ---------------------------------------------------------------------------
extern "C" __global__ void __launch_bounds__(GT, 2)
gemm_proj(const float* __restrict__ X, const float* __restrict__ Wm,
          const float* __restrict__ bias, float* __restrict__ Y, float outScale)
{
    extern __shared__ float smem[];
    float* xs = smem;            // [96][GV=192]
    float* ws = smem + 96 * GV;  // [k][co], row stride WS=100

    const int tid   = threadIdx.x;
    const int vbase = blockIdx.x * GV;

    // Stage X tile (coalesced float4): 96*192/4 = 4608 float4
    for (int i = tid; i < 96 * GV / 4; i += GT) {
        int row = i / (GV / 4);
        int c4  = i - row * (GV / 4);
        const float4* p = reinterpret_cast<const float4*>(X + row * VOX + vbase);
        reinterpret_cast<float4*>(xs)[row * (GV / 4) + c4] = p[c4];
    }
    // Stage W transposed to k-major: ws[k][co] = W[co][k]
    for (int i = tid; i < 96 * 96; i += GT) {
        int co = i / 96;
        int k  = i - co * 96;
        ws[k * WS + co] = Wm[i];
    }
    __syncthreads();

    const int voxg  = tid % 24;        // 0..23 -> 16B lane stride (conflict-free)
    const int coutg = tid / 24;        // 0..11
    const int c0  = coutg * 8;
    const int v0a = voxg * 4;
    const int v0b = v0a + 96;

    u64 acc[8][4];
#pragma unroll
    for (int u = 0; u < 8; u++)
#pragma unroll
        for (int p = 0; p < 4; p++) acc[u][p] = 0ULL;

#pragma unroll 2
    for (int k = 0; k < 96; k++) {
        ulonglong2 b0 = *reinterpret_cast<const ulonglong2*>(&xs[k * GV + v0a]);
        ulonglong2 b1 = *reinterpret_cast<const ulonglong2*>(&xs[k * GV + v0b]);
        float4 w0 = *reinterpret_cast<const float4*>(&ws[k * WS + c0]);
        float4 w1 = *reinterpret_cast<const float4*>(&ws[k * WS + c0 + 4]);
        u64 bp[4] = {b0.x, b0.y, b1.x, b1.y};
        float wv[8] = {w0.x, w0.y, w0.z, w0.w, w1.x, w1.y, w1.z, w1.w};
#pragma unroll
        for (int u = 0; u < 8; u++) {
            u64 ap = splat2(wv[u]);
            acc[u][0] = fma2(ap, bp[0], acc[u][0]);
            acc[u][1] = fma2(ap, bp[1], acc[u][1]);
            acc[u][2] = fma2(ap, bp[2], acc[u][2]);
            acc[u][3] = fma2(ap, bp[3], acc[u][3]);
        }
    }

#pragma unroll
    for (int u = 0; u < 8; u++) {
        float bb = bias[c0 + u];
        float2 p0 = unpack2(acc[u][0]);
        float2 p1 = unpack2(acc[u][1]);
        float2 p2 = unpack2(acc[u][2]);
        float2 p3 = unpack2(acc[u][3]);
        float4 r0 = make_float4((p0.x + bb) * outScale, (p0.y + bb) * outScale,
                                (p1.x + bb) * outScale, (p1.y + bb) * outScale);
        float4 r1 = make_float4((p2.x + bb) * outScale, (p2.y + bb) * outScale,
                                (p3.x + bb) * outScale, (p3.y + bb) * outScale);
        float* yp = Y + (c0 + u) * VOX + vbase;
        *reinterpret_cast<float4*>(yp + v0a) = r0;
        *reinterpret_cast<float4*>(yp + v0b) = r1;
    }
}

// ---------------------------------------------------------------------------
// Attention: one CTA per (window, head), 128 threads.
// Lane pairs (tid, tid^1): each lane owns 12 of 24 dims (half = tid&1) for
// FOUR queries (pid, pid+54, pid+108, pid+162), pid = tid>>1 (clamped to 53;
// writes guarded). Logit halves exchanged via shfl_xor(1). Per key per
// thread: 96 B K+V loads vs 48 FFMA2 -> wavefront:FMA = 1:1 (was 2:1).
// Max-free softmax in exp2 domain (logits bounded; validated since round 4).
// ---------------------------------------------------------------------------
extern "C" __global__ void __launch_bounds__(128, 3)
attn_kernel(const int* __restrict__ use_shift)
{
    __shared__ __align__(16) float ks[NTOK * HD];
    __shared__ __align__(16) float vs[NTOK * HD];
    __shared__ int voxof[NTOK];
    __shared__ int rcode[NTOK];

    const int win  = blockIdx.x >> 2;
    const int head = blockIdx.x & 3;
    const int tid  = threadIdx.x;
    const bool sh  = (use_shift[0] != 0);
    const int shift = sh ? 3 : 0;
    const int wx = win & 7, wy = (win >> 3) & 7, wz = win >> 6;
    const bool needmask = sh && (wx == 7 || wy == 7 || wz == 7);

    for (int t = tid; t < NTOK; t += 128) {
        int tz = t / 36, ty = (t / 6) % 6, tx = t % 6;
        int gz = wz * 6 + tz, gy = wy * 6 + ty, gx = wx * 6 + tx;
        int sz = gz + shift; if (sz >= 48) sz -= 48;
        int sy = gy + shift; if (sy >= 48) sy -= 48;
        int sx = gx + shift; if (sx >= 48) sx -= 48;
        voxof[t] = (sz * 48 + sy) * 48 + sx;
        int rz = gz < 42 ? 0 : (gz < 45 ? 1 : 2);
        int ry = gy < 42 ? 0 : (gy < 45 ? 1 : 2);
        int rx = gx < 42 ? 0 : (gx < 45 ? 1 : 2);
        rcode[t] = rz * 9 + ry * 3 + rx;
    }
    __syncthreads();

    // Stage K and V tiles (coalesced 24B runs in gmem)
    const float* kb = g_k + head * HD * VOX;
    const float* vb = g_v + head * HD * VOX;
    for (int idx = tid; idx < NTOK * HD; idx += 128) {
        int dch = idx / NTOK;
        int j   = idx - dch * NTOK;
        int vx  = voxof[j];
        ks[j * HD + dch] = kb[dch * VOX + vx];
        vs[j * HD + dch] = vb[dch * VOX + vx];
    }
    __syncthreads();

    const int pid  = tid >> 1;
    const int pidc = pid < 54 ? pid : 53;     // clamp so ALL threads run (shfl uniform)
    const int half = tid & 1;
    const int bd   = half * 12;               // my dim base

    int qi[4], vox[4], rr[4];
    const float* bptr[4];
#pragma unroll
    for (int g = 0; g < 4; g++) {
        qi[g]  = pidc + 54 * g;
        vox[g] = voxof[qi[g]];
        rr[g]  = rcode[qi[g]];
        bptr[g] = g_biasT + head * (NTOK * NTOK) + qi[g];
    }

    u64 q2[4][6], o2[4][6];
    float l[4] = {0.f, 0.f, 0.f, 0.f};
#pragma unroll
    for (int g = 0; g < 4; g++) {
        const float* qp = g_q + head * HD * VOX + vox[g];
#pragma unroll
        for (int d = 0; d < 6; d++) {
            q2[g][d] = pack2(qp[(bd + 2 * d) * VOX], qp[(bd + 2 * d + 1) * VOX]);
            o2[g][d] = 0ULL;
        }
    }

    for (int jb = 0; jb < NTOK; jb += 4) {
        // Prefetch bias for 4 keys x 4 queries (covers L2 latency with FMA work)
        float bs[4][4];
#pragma unroll
        for (int kk = 0; kk < 4; kk++)
#pragma unroll
            for (int g = 0; g < 4; g++)
                bs[kk][g] = bptr[g][(jb + kk) * NTOK];
        if (needmask) {
#pragma unroll
            for (int kk = 0; kk < 4; kk++) {
                int rc = rcode[jb + kk];
#pragma unroll
                for (int g = 0; g < 4; g++)
                    if (rc != rr[g]) bs[kk][g] += MASKC;
            }
        }
#pragma unroll
        for (int kk = 0; kk < 4; kk++) {
            int j = jb + kk;
            const ulonglong2* kr = reinterpret_cast<const ulonglong2*>(&ks[j * HD + bd]);
            ulonglong2 k0 = kr[0], k1 = kr[1], k2 = kr[2];

            float shalf[4];
#pragma unroll
            for (int g = 0; g < 4; g++) {
                u64 a0 = fma2(q2[g][0], k0.x, 0ULL);
                u64 a1 = fma2(q2[g][1], k0.y, 0ULL);
                a0 = fma2(q2[g][2], k1.x, a0);
                a1 = fma2(q2[g][3], k1.y, a1);
                a0 = fma2(q2[g][4], k2.x, a0);
                a1 = fma2(q2[g][5], k2.y, a1);
                shalf[g] = hadd2(add2(a0, a1));
            }
            float p[4];
#pragma unroll
            for (int g = 0; g < 4; g++) {
                float oth = __shfl_xor_sync(0xFFFFFFFFu, shalf[g], 1);
                p[g] = ex2f(bs[kk][g] + shalf[g] + oth);
                l[g] += p[g];
            }
            const ulonglong2* vr = reinterpret_cast<const ulonglong2*>(&vs[j * HD + bd]);
            ulonglong2 v0 = vr[0], v1 = vr[1], v2 = vr[2];
#pragma unroll
            for (int g = 0; g < 4; g++) {
                u64 pp = splat2(p[g]);
                o2[g][0] = fma2(pp, v0.x, o2[g][0]);
                o2[g][1] = fma2(pp, v0.y, o2[g][1]);
                o2[g][2] = fma2(pp, v1.x, o2[g][2]);
                o2[g][3] = fma2(pp, v1.y, o2[g][3]);
                o2[g][4] = fma2(pp, v2.x, o2[g][4]);
                o2[g][5] = fma2(pp, v2.y, o2[g][5]);
            }
        }
    }

    if (pid < 54) {
#pragma unroll
        for (int g = 0; g < 4; g++) {
            float inv = 1.0f / l[g];
            float* op = g_o + head * HD * VOX + vox[g];
#pragma unroll
            for (int d = 0; d < 6; d++) {
                float2 v = unpack2(o2[g][d]);
                op[(bd + 2 * d) * VOX]     = v.x * inv;
                op[(bd + 2 * d + 1) * VOX] = v.y * inv;
            }
        }
    }
}

// ---------------------------------------------------------------------------
// kernel_launch
// inputs: 0:q_in 1:k_in 2:v_in 3:Wq 4:bq 5:Wk 6:bk 7:Wv 8:bv 9:Wp 10:bp
//         11:rel_table 12:use_shift
// ---------------------------------------------------------------------------
extern "C" void kernel_launch(void* const* d_in, const int* in_sizes, int n_in,
                              void* d_out, int out_size)
{
    const float* q_in = (const float*)d_in[0];
    const float* k_in = (const float*)d_in[1];
    const float* v_in = (const float*)d_in[2];
    const float* Wq   = (const float*)d_in[3];
    const float* bq   = (const float*)d_in[4];
    const float* Wk   = (const float*)d_in[5];
    const float* bk   = (const float*)d_in[6];
    const float* Wv   = (const float*)d_in[7];
    const float* bv   = (const float*)d_in[8];
    const float* Wp   = (const float*)d_in[9];
    const float* bp   = (const float*)d_in[10];
    const float* rel  = (const float*)d_in[11];
    const int*   ush  = (const int*)d_in[12];

    float *pq, *pk, *pv, *po;
    cudaGetSymbolAddress((void**)&pq, g_q);
    cudaGetSymbolAddress((void**)&pk, g_k);
    cudaGetSymbolAddress((void**)&pv, g_v);
    cudaGetSymbolAddress((void**)&po, g_o);

    const int SMEM_GEMM = (96 * GV + 96 * WS) * (int)sizeof(float);  // 112128
    cudaFuncSetAttribute(gemm_proj, cudaFuncAttributeMaxDynamicSharedMemorySize, SMEM_GEMM);

    const float scale_q = (1.0f / 4.898979485566356f) * LOG2E;  // 24^-0.5 * log2(e)

    bias_prep<<<NTOK, NTOK>>>(rel);
    gemm_proj<<<VOX / GV, GT, SMEM_GEMM>>>(q_in, Wq, bq, pq, scale_q);
    gemm_proj<<<VOX / GV, GT, SMEM_GEMM>>>(k_in, Wk, bk, pk, 1.0f);
    gemm_proj<<<VOX / GV, GT, SMEM_GEMM>>>(v_in, Wv, bv, pv, 1.0f);
    attn_kernel<<<NWIN * NH, 128>>>(ush);
    gemm_proj<<<VOX / GV, GT, SMEM_GEMM>>>(po, Wp, bp, (float*)d_out, 1.0f);
}

// round 12
// speedup vs baseline: 1.0847x; 1.0847x over previous
#include <cuda_runtime.h>

// ---------------------------------------------------------------------------
// CrossWindowAttention3D: 3D shifted-window attention (Video-Swin style)
//   spatial 48^3, C=96, heads=4 (hd=24), window 6^3 (216 tokens), shift 3
// Round 12: GEMM keeps the balanced 8co x 8vox tile (wf:FMA = 1:1) but adds
//   an explicit depth-2 software pipeline so every LDS result is consumed a
//   full compute-block later (fixes the round-11 latency exposure at 18
//   warps). Attention = round-10 measured best (2 queries/thread, 128 thr).
// ---------------------------------------------------------------------------

#define VOX   110592            // 48*48*48
#define NC    96
#define NH    4
#define HD    24
#define NTOK  216               // 6*6*6
#define NWIN  512               // 8*8*8
#define LOG2E 1.4426950408889634f
#define MASKC (-100.0f * LOG2E)
#define WS    100               // W smem row stride (floats); 400 B rows
#define GV    192               // GEMM vox tile
#define GT    288               // GEMM threads

// Scratch (device globals: allocation-free rule)
__device__ float g_q[NC * VOX];
__device__ float g_k[NC * VOX];
__device__ float g_v[NC * VOX];
__device__ float g_o[NC * VOX];
__device__ float g_biasT[NH * NTOK * NTOK];   // [head][key j][query i], *log2(e)

typedef unsigned long long u64;

__device__ __forceinline__ float ex2f(float x) {
    float r;
    asm("ex2.approx.ftz.f32 %0, %1;" : "=f"(r) : "f"(x));
    return r;
}
// packed f32x2 ops (sm_103a FFMA2/FADD2 — only reachable via PTX f32x2 forms)
__device__ __forceinline__ u64 fma2(u64 a, u64 b, u64 c) {
    u64 d;
    asm("fma.rn.f32x2 %0, %1, %2, %3;" : "=l"(d) : "l"(a), "l"(b), "l"(c));
    return d;
}
__device__ __forceinline__ u64 add2(u64 a, u64 b) {
    u64 d;
    asm("add.rn.f32x2 %0, %1, %2;" : "=l"(d) : "l"(a), "l"(b));
    return d;
}
__device__ __forceinline__ u64 splat2(float x) {
    u64 d;
    asm("mov.b64 %0, {%1, %1};" : "=l"(d) : "f"(x));
    return d;
}
__device__ __forceinline__ u64 pack2(float lo, float hi) {
    u64 d;
    asm("mov.b64 %0, {%1, %2};" : "=l"(d) : "f"(lo), "f"(hi));
    return d;
}
__device__ __forceinline__ float hadd2(u64 a) {
    float lo, hi;
    asm("mov.b64 {%0, %1}, %2;" : "=f"(lo), "=f"(hi) : "l"(a));
    return lo + hi;
}
__device__ __forceinline__ float2 unpack2(u64 a) {
    float lo, hi;
    asm("mov.b64 {%0, %1}, %2;" : "=f"(lo), "=f"(hi) : "l"(a));
    return make_float2(lo, hi);
}

// ---------------------------------------------------------------------------
// Relative-position bias table, transposed to [h][j][i], premultiplied log2e.
// ---------------------------------------------------------------------------
extern "C" __global__ void bias_prep(const float* __restrict__ rel_table)
{
    int j = blockIdx.x;      // key token
    int i = threadIdx.x;     // query token
    int iz = i / 36, iy = (i / 6) % 6, ix = i % 6;
    int jz = j / 36, jy = (j / 6) % 6, jx = j % 6;
    int idx = ((iz - jz + 5) * 11 + (iy - jy + 5)) * 11 + (ix - jx + 5);
#pragma unroll
    for (int h = 0; h < NH; h++)
        g_biasT[h * (NTOK * NTOK) + j * NTOK + i] = rel_table[idx * NH + h] * LOG2E;
}

// ---------------------------------------------------------------------------
// GEMM: Y[96][VOX] = (W[96x96] @ X[96][VOX] + bias) * outScale
// CTA: 96 cout x 192 vox, 288 threads, thread tile 8 cout x 8 vox.
// Depth-2 software pipeline: LOAD(k+1); COMP(k); LOAD(k+2); COMP(k+1) —
// each LDS result is consumed one 16-FFMA2 block (~32 issue cyc) after issue.
// ---------------------------------------------------------------------------
extern "C" __global__ void __launch_bounds__(GT, 2)
gemm_proj(const float* __restrict__ X, const float* __restrict__ Wm,
          const float* __restrict__ bias, float* __restrict__ Y, float outScale)
{
    extern __shared__ float smem[];
    float* xs = smem;            // [96][GV=192]
    float* ws = smem + 96 * GV;  // [k][co], row stride WS=100

    const int tid   = threadIdx.x;
    const int vbase = blockIdx.x * GV;

    // Stage X tile (coalesced float4): 96*192/4 = 4608 float4
    for (int i = tid; i < 96 * GV / 4; i += GT) {
        int row = i / (GV / 4);
        int c4  = i - row * (GV / 4);
        const float4* p = reinterpret_cast<const float4*>(X + row * VOX + vbase);
        reinterpret_cast<float4*>(xs)[row * (GV / 4) + c4] = p[c4];
    }
    // Stage W transposed to k-major: ws[k][co] = W[co][k]
    for (int i = tid; i < 96 * 96; i += GT) {
        int co = i / 96;
        int k  = i - co * 96;
        ws[k * WS + co] = Wm[i];
    }
    __syncthreads();

    const int voxg  = tid % 24;        // 16B lane stride -> conflict-free
    const int coutg = tid / 24;        // 0..11
    const int c0  = coutg * 8;
    const int v0a = voxg * 4;
    const int v0b = v0a + 96;

    u64 acc[8][4];
#pragma unroll
    for (int u = 0; u < 8; u++)
#pragma unroll
        for (int p = 0; p < 4; p++) acc[u][p] = 0ULL;

#define LOADK(K, B0, B1, W0, W1)                                              \
    B0 = *reinterpret_cast<const ulonglong2*>(&xs[(K) * GV + v0a]);           \
    B1 = *reinterpret_cast<const ulonglong2*>(&xs[(K) * GV + v0b]);           \
    W0 = *reinterpret_cast<const float4*>(&ws[(K) * WS + c0]);                \
    W1 = *reinterpret_cast<const float4*>(&ws[(K) * WS + c0 + 4]);

#define COMPK(B0, B1, W0, W1)                                                 \
    {                                                                         \
        u64 bp0 = B0.x, bp1 = B0.y, bp2 = B1.x, bp3 = B1.y;                   \
        float wv[8] = {W0.x, W0.y, W0.z, W0.w, W1.x, W1.y, W1.z, W1.w};       \
        _Pragma("unroll")                                                     \
        for (int u = 0; u < 8; u++) {                                         \
            u64 ap = splat2(wv[u]);                                           \
            acc[u][0] = fma2(ap, bp0, acc[u][0]);                             \
            acc[u][1] = fma2(ap, bp1, acc[u][1]);                             \
            acc[u][2] = fma2(ap, bp2, acc[u][2]);                             \
            acc[u][3] = fma2(ap, bp3, acc[u][3]);                             \
        }                                                                     \
    }

    ulonglong2 ab0, ab1, bb0, bb1;
    float4 aw0, aw1, bw0, bw1;

    LOADK(0, ab0, ab1, aw0, aw1);
    for (int k = 0; k < 94; k += 2) {
        LOADK(k + 1, bb0, bb1, bw0, bw1);
        COMPK(ab0, ab1, aw0, aw1);
        LOADK(k + 2, ab0, ab1, aw0, aw1);
        COMPK(bb0, bb1, bw0, bw1);
    }
    // peel: a holds k=94
    LOADK(95, bb0, bb1, bw0, bw1);
    COMPK(ab0, ab1, aw0, aw1);
    COMPK(bb0, bb1, bw0, bw1);

#undef LOADK
#undef COMPK

#pragma unroll
    for (int u = 0; u < 8; u++) {
        float bb = bias[c0 + u];
        float2 p0 = unpack2(acc[u][0]);
        float2 p1 = unpack2(acc[u][1]);
        float2 p2 = unpack2(acc[u][2]);
        float2 p3 = unpack2(acc[u][3]);
        float4 r0 = make_float4((p0.x + bb) * outScale, (p0.y + bb) * outScale,
                                (p1.x + bb) * outScale, (p1.y + bb) * outScale);
        float4 r1 = make_float4((p2.x + bb) * outScale, (p2.y + bb) * outScale,
                                (p3.x + bb) * outScale, (p3.y + bb) * outScale);
        float* yp = Y + (c0 + u) * VOX + vbase;
        *reinterpret_cast<float4*>(yp + v0a) = r0;
        *reinterpret_cast<float4*>(yp + v0b) = r1;
    }
}

// ---------------------------------------------------------------------------
// Attention (round-10 measured best): one CTA per (window, head), 128 threads;
// threads 0..107 each own TWO query rows (tid, tid+108). Max-free softmax in
// exp2 domain (logits bounded; validated since round 4).
// ---------------------------------------------------------------------------
extern "C" __global__ void __launch_bounds__(128, 3)
attn_kernel(const int* __restrict__ use_shift)
{
    __shared__ __align__(16) float ks[NTOK * HD];
    __shared__ __align__(16) float vs[NTOK * HD];
    __shared__ int voxof[NTOK];
    __shared__ int rcode[NTOK];

    const int win  = blockIdx.x >> 2;
    const int head = blockIdx.x & 3;
    const int tid  = threadIdx.x;
    const bool sh  = (use_shift[0] != 0);
    const int shift = sh ? 3 : 0;
    const int wx = win & 7, wy = (win >> 3) & 7, wz = win >> 6;
    const bool needmask = sh && (wx == 7 || wy == 7 || wz == 7);

    for (int t = tid; t < NTOK; t += 128) {
        int tz = t / 36, ty = (t / 6) % 6, tx = t % 6;
        int gz = wz * 6 + tz, gy = wy * 6 + ty, gx = wx * 6 + tx;
        int sz = gz + shift; if (sz >= 48) sz -= 48;
        int sy = gy + shift; if (sy >= 48) sy -= 48;
        int sx = gx + shift; if (sx >= 48) sx -= 48;
        voxof[t] = (sz * 48 + sy) * 48 + sx;
        int rz = gz < 42 ? 0 : (gz < 45 ? 1 : 2);
        int ry = gy < 42 ? 0 : (gy < 45 ? 1 : 2);
        int rx = gx < 42 ? 0 : (gx < 45 ? 1 : 2);
        rcode[t] = rz * 9 + ry * 3 + rx;
    }
    __syncthreads();

    // Stage K and V tiles (coalesced 24B runs in gmem)
    const float* kb = g_k + head * HD * VOX;
    const float* vb = g_v + head * HD * VOX;
    for (int idx = tid; idx < NTOK * HD; idx += 128) {
        int dch = idx / NTOK;
        int j   = idx - dch * NTOK;
        int vx  = voxof[j];
        ks[j * HD + dch] = kb[dch * VOX + vx];
        vs[j * HD + dch] = vb[dch * VOX + vx];
    }

    u64 qa[12], qb[12], oa[12], ob[12];
    float la0 = 0.f, la1 = 0.f, lb0 = 0.f, lb1 = 0.f;
    int voxA = 0, voxB = 0, rA = 0, rB = 0;
    if (tid < 108) {
        voxA = voxof[tid];       rA = rcode[tid];
        voxB = voxof[tid + 108]; rB = rcode[tid + 108];
        const float* qpA = g_q + head * HD * VOX + voxA;
        const float* qpB = g_q + head * HD * VOX + voxB;
#pragma unroll
        for (int d = 0; d < 12; d++) {
            qa[d] = pack2(qpA[(2 * d) * VOX], qpA[(2 * d + 1) * VOX]);
            qb[d] = pack2(qpB[(2 * d) * VOX], qpB[(2 * d + 1) * VOX]);
        }
    }
#pragma unroll
    for (int d = 0; d < 12; d++) { oa[d] = 0ULL; ob[d] = 0ULL; }
    __syncthreads();

    if (tid < 108) {
        const float* biasA = g_biasT + head * (NTOK * NTOK) + tid;
        const float* biasB = biasA + 108;
        for (int jb = 0; jb < NTOK; jb += 8) {
            float sA[8], sB[8];
#pragma unroll
            for (int g = 0; g < 8; g++) {
                sA[g] = biasA[(jb + g) * NTOK];
                sB[g] = biasB[(jb + g) * NTOK];
            }
            if (needmask) {
#pragma unroll
                for (int g = 0; g < 8; g++) {
                    int rc = rcode[jb + g];
                    if (rc != rA) sA[g] += MASKC;
                    if (rc != rB) sB[g] += MASKC;
                }
            }
#pragma unroll
            for (int g = 0; g < 8; g++) {
                int j = jb + g;
                const ulonglong2* kr = reinterpret_cast<const ulonglong2*>(&ks[j * HD]);
                ulonglong2 k0 = kr[0], k1 = kr[1], k2 = kr[2];
                ulonglong2 k3 = kr[3], k4 = kr[4], k5 = kr[5];

                u64 aA0 = fma2(qa[0], k0.x, 0ULL);
                u64 aA1 = fma2(qa[1], k0.y, 0ULL);
                u64 aB0 = fma2(qb[0], k0.x, 0ULL);
                u64 aB1 = fma2(qb[1], k0.y, 0ULL);
                aA0 = fma2(qa[2], k1.x, aA0);  aA1 = fma2(qa[3], k1.y, aA1);
                aB0 = fma2(qb[2], k1.x, aB0);  aB1 = fma2(qb[3], k1.y, aB1);
                aA0 = fma2(qa[4], k2.x, aA0);  aA1 = fma2(qa[5], k2.y, aA1);
                aB0 = fma2(qb[4], k2.x, aB0);  aB1 = fma2(qb[5], k2.y, aB1);
                aA0 = fma2(qa[6], k3.x, aA0);  aA1 = fma2(qa[7], k3.y, aA1);
                aB0 = fma2(qb[6], k3.x, aB0);  aB1 = fma2(qb[7], k3.y, aB1);
                aA0 = fma2(qa[8], k4.x, aA0);  aA1 = fma2(qa[9], k4.y, aA1);
                aB0 = fma2(qb[8], k4.x, aB0);  aB1 = fma2(qb[9], k4.y, aB1);
                aA0 = fma2(qa[10], k5.x, aA0); aA1 = fma2(qa[11], k5.y, aA1);
                aB0 = fma2(qb[10], k5.x, aB0); aB1 = fma2(qb[11], k5.y, aB1);

                float pA = ex2f(sA[g] + hadd2(add2(aA0, aA1)));
                float pB = ex2f(sB[g] + hadd2(add2(aB0, aB1)));
                if (g & 1) { la1 += pA; lb1 += pB; }
                else       { la0 += pA; lb0 += pB; }
                u64 ppA = splat2(pA);
                u64 ppB = splat2(pB);

                const ulonglong2* vr = reinterpret_cast<const ulonglong2*>(&vs[j * HD]);
                ulonglong2 v0 = vr[0], v1 = vr[1], v2 = vr[2];
                ulonglong2 v3 = vr[3], v4 = vr[4], v5 = vr[5];
                oa[0]  = fma2(ppA, v0.x, oa[0]);   ob[0]  = fma2(ppB, v0.x, ob[0]);
                oa[1]  = fma2(ppA, v0.y, oa[1]);   ob[1]  = fma2(ppB, v0.y, ob[1]);
                oa[2]  = fma2(ppA, v1.x, oa[2]);   ob[2]  = fma2(ppB, v1.x, ob[2]);
                oa[3]  = fma2(ppA, v1.y, oa[3]);   ob[3]  = fma2(ppB, v1.y, ob[3]);
                oa[4]  = fma2(ppA, v2.x, oa[4]);   ob[4]  = fma2(ppB, v2.x, ob[4]);
                oa[5]  = fma2(ppA, v2.y, oa[5]);   ob[5]  = fma2(ppB, v2.y, ob[5]);
                oa[6]  = fma2(ppA, v3.x, oa[6]);   ob[6]  = fma2(ppB, v3.x, ob[6]);
                oa[7]  = fma2(ppA, v3.y, oa[7]);   ob[7]  = fma2(ppB, v3.y, ob[7]);
                oa[8]  = fma2(ppA, v4.x, oa[8]);   ob[8]  = fma2(ppB, v4.x, ob[8]);
                oa[9]  = fma2(ppA, v4.y, oa[9]);   ob[9]  = fma2(ppB, v4.y, ob[9]);
                oa[10] = fma2(ppA, v5.x, oa[10]);  ob[10] = fma2(ppB, v5.x, ob[10]);
                oa[11] = fma2(ppA, v5.y, oa[11]);  ob[11] = fma2(ppB, v5.y, ob[11]);
            }
        }
        float invA = 1.0f / (la0 + la1);
        float invB = 1.0f / (lb0 + lb1);
        float* opA = g_o + head * HD * VOX + voxA;
        float* opB = g_o + head * HD * VOX + voxB;
#pragma unroll
        for (int d = 0; d < 12; d++) {
            float2 va = unpack2(oa[d]);
            float2 vb2 = unpack2(ob[d]);
            opA[(2 * d) * VOX]     = va.x * invA;
            opA[(2 * d + 1) * VOX] = va.y * invA;
            opB[(2 * d) * VOX]     = vb2.x * invB;
            opB[(2 * d + 1) * VOX] = vb2.y * invB;
        }
    }
}

// ---------------------------------------------------------------------------
// kernel_launch
// inputs: 0:q_in 1:k_in 2:v_in 3:Wq 4:bq 5:Wk 6:bk 7:Wv 8:bv 9:Wp 10:bp
//         11:rel_table 12:use_shift
// ---------------------------------------------------------------------------
extern "C" void kernel_launch(void* const* d_in, const int* in_sizes, int n_in,
                              void* d_out, int out_size)
{
    const float* q_in = (const float*)d_in[0];
    const float* k_in = (const float*)d_in[1];
    const float* v_in = (const float*)d_in[2];
    const float* Wq   = (const float*)d_in[3];
    const float* bq   = (const float*)d_in[4];
    const float* Wk   = (const float*)d_in[5];
    const float* bk   = (const float*)d_in[6];
    const float* Wv   = (const float*)d_in[7];
    const float* bv   = (const float*)d_in[8];
    const float* Wp   = (const float*)d_in[9];
    const float* bp   = (const float*)d_in[10];
    const float* rel  = (const float*)d_in[11];
    const int*   ush  = (const int*)d_in[12];

    float *pq, *pk, *pv, *po;
    cudaGetSymbolAddress((void**)&pq, g_q);
    cudaGetSymbolAddress((void**)&pk, g_k);
    cudaGetSymbolAddress((void**)&pv, g_v);
    cudaGetSymbolAddress((void**)&po, g_o);

    const int SMEM_GEMM = (96 * GV + 96 * WS) * (int)sizeof(float);  // 112128
    cudaFuncSetAttribute(gemm_proj, cudaFuncAttributeMaxDynamicSharedMemorySize, SMEM_GEMM);

    const float scale_q = (1.0f / 4.898979485566356f) * LOG2E;  // 24^-0.5 * log2(e)

    bias_prep<<<NTOK, NTOK>>>(rel);
    gemm_proj<<<VOX / GV, GT, SMEM_GEMM>>>(q_in, Wq, bq, pq, scale_q);
    gemm_proj<<<VOX / GV, GT, SMEM_GEMM>>>(k_in, Wk, bk, pk, 1.0f);
    gemm_proj<<<VOX / GV, GT, SMEM_GEMM>>>(v_in, Wv, bv, pv, 1.0f);
    attn_kernel<<<NWIN * NH, 128>>>(ush);
    gemm_proj<<<VOX / GV, GT, SMEM_GEMM>>>(po, Wp, bp, (float*)d_out, 1.0f);
}